// round 13
// baseline (speedup 1.0000x reference)
#include <cuda_runtime.h>
#include <cuda_fp16.h>
#include <cstdint>

// ---------------- problem constants ----------------
#define TOK   16384
#define HD    1024
#define IDM   1024
#define NE    8
#define MAXMT 264                 // ceil(32768/128) + 8 experts of padding slack
#define PMAX  (MAXMT * 128)       // 33792 padded pair capacity
#define W1Q   (NE * 2 * IDM * HD / 4)   // 4194304 float4 units
#define W2Q   (NE * HD * IDM / 4)       // 2097152
#define WCB   ((W1Q + W2Q) / 256)       // 24576 weight-convert blocks
#define XB    (TOK * HD / 4 / 256)      // 16384 x-convert blocks
#define ZB    (PMAX / 256)              // 132 zeroing blocks
#define RB    (TOK / 256)               // 64 router/scatter blocks

// ---------------- device scratch (no allocs allowed) ----------------
__device__ __half g_w1h[NE * 2 * IDM * HD];     // fp16 raw w1 (33.5 MB)
__device__ __half g_w2h[NE * HD * IDM];         // fp16 raw w2 (16.8 MB)
__device__ __half g_xh[(size_t)TOK * HD];       // x in fp16 (ungathered, 33.5 MB)
__device__ __half g_hh[(size_t)PMAX * IDM];     // SwiGLU h (fp16)
__device__ __half g_yh[(size_t)PMAX * HD];      // per-pair outputs (fp16)
__device__ int    g_pair_tok[PMAX];
__device__ float  g_pair_coef[PMAX];
__device__ int    g_tk_idx[TOK * 2];
__device__ float  g_tk_w[TOK * 2];
__device__ int    g_tok_pos[TOK * 2];
__device__ int    g_cur[NE];
__device__ int    g_tile_e[MAXMT];
__device__ int    g_tile_m0[MAXMT];
__device__ int    g_nmt;
__device__ int    g_flag;

// ---------------- helpers ----------------
__device__ __forceinline__ uint32_t smem_u32(const void* p) {
    uint32_t a;
    asm("{ .reg .u64 t; cvta.to.shared.u64 t, %1; cvt.u32.u64 %0, t; }" : "=r"(a) : "l"(p));
    return a;
}
__device__ __forceinline__ uint32_t swz(uint32_t o) { return o ^ ((o >> 3) & 0x70); }

__device__ __forceinline__ void cp16(uint32_t dst, const void* src) {
    asm volatile("cp.async.cg.shared.global [%0], [%1], 16;" :: "r"(dst), "l"(src));
}
#define CP_COMMIT() asm volatile("cp.async.commit_group;" ::: "memory")
#define CP_WAIT(n)  asm volatile("cp.async.wait_group %0;" :: "n"(n) : "memory")

__device__ __forceinline__ void ldsm_x4(uint32_t& r0, uint32_t& r1, uint32_t& r2, uint32_t& r3,
                                        uint32_t addr) {
    asm volatile("ldmatrix.sync.aligned.m8n8.x4.shared.b16 {%0,%1,%2,%3}, [%4];"
                 : "=r"(r0), "=r"(r1), "=r"(r2), "=r"(r3) : "r"(addr));
}
__device__ __forceinline__ void mma16816(float* d, uint32_t a0, uint32_t a1, uint32_t a2,
                                         uint32_t a3, uint32_t b0, uint32_t b1) {
    asm volatile(
        "mma.sync.aligned.m16n8k16.row.col.f32.f16.f16.f32 "
        "{%0,%1,%2,%3}, {%4,%5,%6,%7}, {%8,%9}, {%0,%1,%2,%3};"
        : "+f"(d[0]), "+f"(d[1]), "+f"(d[2]), "+f"(d[3])
        : "r"(a0), "r"(a1), "r"(a2), "r"(a3), "r"(b0), "r"(b1));
}

// ---------------- k_route: zero pads/flags + router ----------------
__global__ void k_route(const float* __restrict__ gating) {
    int b = blockIdx.x, tid = threadIdx.x;
    if (b < ZB) {
        int i = b * 256 + tid;
        g_pair_tok[i] = 0;
        g_pair_coef[i] = 0.f;
        if (i == 0) g_flag = 0;
    } else {
        // router: top-2 softmax, renormalized (denominator cancels)
        int t = (b - ZB) * 256 + tid;
        float l[NE];
#pragma unroll
        for (int e = 0; e < NE; e++) l[e] = gating[t * NE + e];
        int i0 = 0; float b0 = l[0];
#pragma unroll
        for (int e = 1; e < NE; e++) if (l[e] > b0) { b0 = l[e]; i0 = e; }
        int i1 = -1; float b1 = -3.4e38f;
#pragma unroll
        for (int e = 0; e < NE; e++) if (e != i0 && l[e] > b1) { b1 = l[e]; i1 = e; }
        float r = __expf(b1 - b0);
        float inv = 1.f / (1.f + r);
        g_tk_idx[t * 2] = i0;  g_tk_idx[t * 2 + 1] = i1;
        g_tk_w[t * 2] = inv;   g_tk_w[t * 2 + 1] = r * inv;
    }
}

// ---------------- k_mega: scatter | xconv | wconv (mutually independent) -----
__global__ void __launch_bounds__(256, 8)
k_mega(const float* __restrict__ x, const float* __restrict__ w1,
       const float* __restrict__ w2) {
    int b = blockIdx.x, tid = threadIdx.x;
    if (b < RB) {
        // ---- scatter role (block0 computes hist+offsets, others spin) ----
        if (b == 0) {
            __shared__ int hist[NE];
            if (tid < NE) hist[tid] = 0;
            __syncthreads();
            for (int i = tid; i < TOK * 2; i += 256) atomicAdd(&hist[g_tk_idx[i]], 1);
            __syncthreads();
            if (tid == 0) {
                int off = 0, ntl = 0;
                for (int e = 0; e < NE; e++) {
                    int c = hist[e];
                    g_cur[e] = off;
                    int mts = (c + 127) >> 7;
                    for (int j = 0; j < mts; j++) {
                        g_tile_e[ntl] = e; g_tile_m0[ntl] = off + j * 128; ntl++;
                    }
                    off += mts * 128;
                }
                g_nmt = ntl;
                __threadfence();
                atomicExch(&g_flag, 1);
            }
        }
        if (tid == 0) { while (atomicAdd(&g_flag, 0) == 0) { __nanosleep(100); } }
        __syncthreads();
        int t = b * 256 + tid;
#pragma unroll
        for (int k = 0; k < 2; k++) {
            int e = g_tk_idx[t * 2 + k];
            int pos = atomicAdd(&g_cur[e], 1);
            g_pair_tok[pos] = t;
            g_pair_coef[pos] = g_tk_w[t * 2 + k];
            g_tok_pos[t * 2 + k] = pos;
        }
    } else if (b < RB + XB) {
        // ---- xconv role: x fp32 -> fp16 (ungathered) ----
        int i = (b - RB) * 256 + tid;
        float4 v = ((const float4*)x)[i];
        __half2 hh0 = __halves2half2(__float2half_rn(v.x), __float2half_rn(v.y));
        __half2 hh1 = __halves2half2(__float2half_rn(v.z), __float2half_rn(v.w));
        uint2 uh; uh.x = *(uint32_t*)&hh0; uh.y = *(uint32_t*)&hh1;
        *(uint2*)(g_xh + (size_t)i * 4) = uh;
    } else {
        // ---- wconv role: fp32 -> fp16 weights ----
        int i = (b - RB - XB) * 256 + tid;
        const float4* src; __half* dst; int q;
        if (i < W1Q) { src = (const float4*)w1; dst = g_w1h; q = i; }
        else         { src = (const float4*)w2; dst = g_w2h; q = i - W1Q; }
        float4 v = src[q];
        __half2 h01 = __halves2half2(__float2half_rn(v.x), __float2half_rn(v.y));
        __half2 h23 = __halves2half2(__float2half_rn(v.z), __float2half_rn(v.w));
        uint2 u; u.x = *(uint32_t*)&h01; u.y = *(uint32_t*)&h23;
        *(uint2*)(dst + (size_t)q * 4) = u;
    }
}

__global__ void k_combine(float* __restrict__ out) {
    int idx = blockIdx.x * blockDim.x + threadIdx.x;   // float4 outputs, TOK*256 total
    if (idx >= TOK * 256) return;
    int t = idx >> 8;
    int c4 = idx & 255;
    int p0 = g_tok_pos[t * 2];
    int p1 = g_tok_pos[t * 2 + 1];
    uint2 ua = *(const uint2*)(g_yh + (size_t)p0 * 1024 + c4 * 4);
    uint2 ub = *(const uint2*)(g_yh + (size_t)p1 * 1024 + c4 * 4);
    float2 a0 = __half22float2(*(__half2*)&ua.x);
    float2 a1 = __half22float2(*(__half2*)&ua.y);
    float2 b0 = __half22float2(*(__half2*)&ub.x);
    float2 b1 = __half22float2(*(__half2*)&ub.y);
    float4 o;
    o.x = a0.x + b0.x; o.y = a0.y + b0.y;
    o.z = a1.x + b1.x; o.w = a1.y + b1.y;
    ((float4*)out)[idx] = o;
}

// ---------------- GEMM (R12 config + pipelined fragments) --------------------
// CTA: 128 threads = 4 warps (2M x 2N), CTA tile 128(M) x 64(N-rows), K=64.
// Warp tile 64x32. Stage = 24KB, NSTG=3, 3 CTAs/SM.
// Inner-loop change vs R12: A fragments rotate through a 2-deep buffer, with
// ldsm A(step s+1) issued BEFORE the mma burst of step s (4-mma issue window
// covers the ~30cyc ldsm latency). B reload for ks+1 issues AFTER the last mma
// group of ks (WAR only). +4 regs vs R12 (158 -> ~162, cap 170).
// STAGE 1: A rows gathered from ungathered g_xh via smem tok table; B rows
//   interleave gate/up in 16-row blocks (loader rows r=r0+16j => blk=j, w=r0).
// STAGE 2: plain rows; grid nt-fastest for L2 A-tile sharing.
#define SM_STG 1024
#define SB_OF  16384
#define STGSZ  24576
#define NSTG   3
#define SMEMB  (SM_STG + NSTG * STGSZ)   // 74752

template <int STAGE>
__global__ void __launch_bounds__(128, 3)
k_gemm(const float* __restrict__ w1s, const float* __restrict__ w2s) {
    const int NT = (STAGE == 1) ? 32 : 16;
    int bmt = blockIdx.x / NT;
    int nt  = blockIdx.x % NT;
    if (bmt >= g_nmt) return;
    int e  = g_tile_e[bmt];
    int m0 = g_tile_m0[bmt];

    extern __shared__ __align__(1024) char smem[];
    uint32_t sb = smem_u32(smem);
    int* s_tok = (int*)smem;
    int tid = threadIdx.x, lane = tid & 31, wid = tid >> 5;
    int wm = wid >> 1, wn = wid & 1;

    const __half* A = (STAGE == 1) ? g_xh : g_hh;
    const __half* W = (STAGE == 1) ? g_w1h : g_w2h;

    if (STAGE == 1) {
        s_tok[tid] = g_pair_tok[m0 + tid];
        __syncthreads();
    }

    int r0 = tid >> 3, c0 = tid & 7;
    uint32_t dA0 = swz((uint32_t)(r0 * 128 + c0 * 16));   // byte offset, +2048/j
    uint32_t offA[8];                                     // half-element offsets
#pragma unroll
    for (int j = 0; j < 8; j++) {
        int row = (STAGE == 1) ? s_tok[r0 + 16 * j] : (m0 + r0 + 16 * j);
        offA[j] = (uint32_t)row * 1024 + c0 * 8;
    }
    // B base: rows r=r0+16j (j<4). STAGE1: blk=j, w=r0.
    uint32_t offB0 = (STAGE == 1)
        ? (uint32_t)(e * 2048 + nt * 32 + r0) * 1024 + c0 * 8
        : (uint32_t)(e * 1024 + nt * 64 + r0) * 1024 + c0 * 8;
    const uint32_t BC1_0 = 0u, BC1_1 = 1024u * 1024u, BC1_2 = 16u * 1024u,
                   BC1_3 = 1040u * 1024u;

    float acc[4][4][4];
#pragma unroll
    for (int a = 0; a < 4; a++)
#pragma unroll
        for (int b = 0; b < 4; b++)
#pragma unroll
            for (int c = 0; c < 4; c++) acc[a][b][c] = 0.f;

#define LOAD_CHUNK(base, ko)                                                     \
    do {                                                                         \
        _Pragma("unroll")                                                        \
        for (int j = 0; j < 8; j++)                                              \
            cp16((base) + dA0 + j * 2048, A + offA[j] + (ko));                   \
        if (STAGE == 1) {                                                        \
            cp16((base) + SB_OF + dA0 + 0 * 2048, W + offB0 + BC1_0 + (ko));     \
            cp16((base) + SB_OF + dA0 + 1 * 2048, W + offB0 + BC1_1 + (ko));     \
            cp16((base) + SB_OF + dA0 + 2 * 2048, W + offB0 + BC1_2 + (ko));     \
            cp16((base) + SB_OF + dA0 + 3 * 2048, W + offB0 + BC1_3 + (ko));     \
        } else {                                                                 \
            _Pragma("unroll")                                                    \
            for (int j = 0; j < 4; j++)                                          \
                cp16((base) + SB_OF + dA0 + j * 2048, W + offB0 + j * 16384 + (ko)); \
        }                                                                        \
        CP_COMMIT();                                                             \
    } while (0)

#define A_ADDR(ks_, mt_) (bufb + swz((uint32_t)((wm * 64 + (mt_) * 16 + ((grp & 1) << 3) + lr) * 128 \
                                               + ((ks_) * 16 + ((grp >> 1) << 3)) * 2)))
#define B_ADDR(ks_, p_)  (bufb + SB_OF + swz((uint32_t)((wn * 32 + (p_) * 16 + ((grp >> 1) << 3) + lr) * 128 \
                                               + ((ks_) * 16 + ((grp & 1) << 3)) * 2)))

    // prologue: load chunks 0,1
    LOAD_CHUNK(sb + SM_STG, 0);
    LOAD_CHUNK(sb + SM_STG + STGSZ, 64);

    int buf = 0;      // buffer index of current chunk kc (kc % 3)
#pragma unroll 1
    for (int kc = 0; kc < 16; kc++) {
        if (kc + 2 < 16) {
            int nb = buf + 2; if (nb >= NSTG) nb -= NSTG;
            LOAD_CHUNK(sb + SM_STG + nb * STGSZ, (kc + 2) * 64);
            CP_WAIT(2);
        } else if (kc + 1 < 16) {
            CP_WAIT(1);
        } else {
            CP_WAIT(0);
        }
        __syncthreads();

        uint32_t bufb = sb + SM_STG + buf * STGSZ;
        int grp = lane >> 3, lr = lane & 7;

        // ---- pipelined fragment schedule ----
        uint32_t bf[8];          // B frags for current ks (4 n8-tiles)
        uint32_t af[2][4];       // A frag double buffer
        ldsm_x4(bf[0], bf[1], bf[2], bf[3], B_ADDR(0, 0));
        ldsm_x4(bf[4], bf[5], bf[6], bf[7], B_ADDR(0, 1));
        ldsm_x4(af[0][0], af[0][1], af[0][2], af[0][3], A_ADDR(0, 0));
#pragma unroll
        for (int s = 0; s < 16; s++) {
            int ks = s >> 2, mt = s & 3;
            int cur = s & 1, nxt = cur ^ 1;
            if (s < 15) {
                int nks = (s + 1) >> 2, nmt = (s + 1) & 3;
                ldsm_x4(af[nxt][0], af[nxt][1], af[nxt][2], af[nxt][3],
                        A_ADDR(nks, nmt));
            }
#pragma unroll
            for (int n8 = 0; n8 < 4; n8++)
                mma16816(acc[mt][n8], af[cur][0], af[cur][1], af[cur][2], af[cur][3],
                         bf[2 * n8], bf[2 * n8 + 1]);
            if (mt == 3 && ks < 3) {
                ldsm_x4(bf[0], bf[1], bf[2], bf[3], B_ADDR(ks + 1, 0));
                ldsm_x4(bf[4], bf[5], bf[6], bf[7], B_ADDR(ks + 1, 1));
            }
        }
        __syncthreads();
        buf++; if (buf >= NSTG) buf = 0;
    }

    // ---------------- epilogue ----------------
    if (STAGE == 1) {
        float s1 = w1s[e];
#pragma unroll
        for (int mt = 0; mt < 4; mt++) {
            int r0e = m0 + wm * 64 + mt * 16 + (lane >> 2);
#pragma unroll
            for (int i = 0; i < 2; i++) {
                int col = nt * 32 + wn * 16 + i * 8 + (lane & 3) * 2;
#pragma unroll
                for (int hh = 0; hh < 2; hh++) {
                    int rr = r0e + hh * 8;
                    float g0 = s1 * acc[mt][i][2 * hh + 0];
                    float g1 = s1 * acc[mt][i][2 * hh + 1];
                    float u0 = s1 * acc[mt][i + 2][2 * hh + 0];
                    float u1 = s1 * acc[mt][i + 2][2 * hh + 1];
                    float h0 = g0 * (1.f / (1.f + __expf(-g0))) * u0;
                    float h1 = g1 * (1.f / (1.f + __expf(-g1))) * u1;
                    *(__half2*)(g_hh + (size_t)rr * 1024 + col) =
                        __halves2half2(__float2half_rn(h0), __float2half_rn(h1));
                }
            }
        }
    } else {
        float s2 = w2s[e];
#pragma unroll
        for (int mt = 0; mt < 4; mt++) {
            int r0e = m0 + wm * 64 + mt * 16 + (lane >> 2);
#pragma unroll
            for (int hh = 0; hh < 2; hh++) {
                int rr = r0e + hh * 8;
                float sc = g_pair_coef[rr] * s2;
#pragma unroll
                for (int i = 0; i < 4; i++) {
                    int col = nt * 64 + wn * 32 + i * 8 + (lane & 3) * 2;
                    float y0 = sc * acc[mt][i][2 * hh + 0];
                    float y1 = sc * acc[mt][i][2 * hh + 1];
                    *(__half2*)(g_yh + (size_t)rr * 1024 + col) =
                        __halves2half2(__float2half_rn(y0), __float2half_rn(y1));
                }
            }
        }
    }
#undef LOAD_CHUNK
#undef A_ADDR
#undef B_ADDR
}

// ---------------- launch ----------------
extern "C" void kernel_launch(void* const* d_in, const int* in_sizes, int n_in,
                              void* d_out, int out_size) {
    const float* x      = (const float*)d_in[0];
    const float* gating = (const float*)d_in[1];
    const float* w1     = (const float*)d_in[2];
    const float* w2     = (const float*)d_in[3];
    const float* w1s    = (const float*)d_in[4];
    const float* w2s    = (const float*)d_in[5];
    float* out = (float*)d_out;

    cudaFuncSetAttribute(k_gemm<1>, cudaFuncAttributeMaxDynamicSharedMemorySize, SMEMB);
    cudaFuncSetAttribute(k_gemm<2>, cudaFuncAttributeMaxDynamicSharedMemorySize, SMEMB);

    k_route<<<ZB + RB, 256>>>(gating);
    k_mega<<<RB + XB + WCB, 256>>>(x, w1, w2);
    k_gemm<1><<<MAXMT * 32, 128, SMEMB>>>(w1s, w2s);   // ncu captures this launch
    k_gemm<2><<<MAXMT * 16, 128, SMEMB>>>(w1s, w2s);
    k_combine<<<TOK, 256>>>(out);
}

// round 14
// speedup vs baseline: 1.4850x; 1.4850x over previous
#include <cuda_runtime.h>
#include <cuda_fp16.h>
#include <cstdint>

// ---------------- problem constants ----------------
#define TOK   16384
#define HD    1024
#define IDM   1024
#define NE    8
#define MAXMT 264                 // ceil(32768/128) + 8 experts of padding slack
#define PMAX  (MAXMT * 128)       // 33792 padded pair capacity
#define W1Q   (NE * 2 * IDM * HD / 4)   // 4194304 float4 units
#define W2Q   (NE * HD * IDM / 4)       // 2097152
#define WCB   ((W1Q + W2Q) / 256)       // 24576 weight-convert blocks
#define XB    (TOK * HD / 4 / 256)      // 16384 x-convert blocks
#define ZB    (PMAX / 256)              // 132 zeroing blocks
#define RB    (TOK / 256)               // 64 router/scatter blocks

// ---------------- device scratch (no allocs allowed) ----------------
__device__ __half g_w1h[NE * 2 * IDM * HD];     // fp16 raw w1 (33.5 MB)
__device__ __half g_w2h[NE * HD * IDM];         // fp16 raw w2 (16.8 MB)
__device__ __half g_xh[(size_t)TOK * HD];       // x in fp16 (ungathered, 33.5 MB)
__device__ __half g_hh[(size_t)PMAX * IDM];     // SwiGLU h (fp16)
__device__ __half g_yh[(size_t)PMAX * HD];      // per-pair outputs (fp16)
__device__ int    g_pair_tok[PMAX];
__device__ float  g_pair_coef[PMAX];
__device__ int    g_tk_idx[TOK * 2];
__device__ float  g_tk_w[TOK * 2];
__device__ int    g_tok_pos[TOK * 2];
__device__ int    g_cur[NE];
__device__ int    g_tile_e[MAXMT];
__device__ int    g_tile_m0[MAXMT];
__device__ int    g_nmt;
__device__ int    g_flag;

// ---------------- helpers ----------------
__device__ __forceinline__ uint32_t smem_u32(const void* p) {
    uint32_t a;
    asm("{ .reg .u64 t; cvta.to.shared.u64 t, %1; cvt.u32.u64 %0, t; }" : "=r"(a) : "l"(p));
    return a;
}
__device__ __forceinline__ uint32_t swz(uint32_t o) { return o ^ ((o >> 3) & 0x70); }

__device__ __forceinline__ void cp16(uint32_t dst, const void* src) {
    asm volatile("cp.async.cg.shared.global [%0], [%1], 16;" :: "r"(dst), "l"(src));
}
#define CP_COMMIT() asm volatile("cp.async.commit_group;" ::: "memory")
#define CP_WAIT(n)  asm volatile("cp.async.wait_group %0;" :: "n"(n) : "memory")

__device__ __forceinline__ void ldsm_x4(uint32_t& r0, uint32_t& r1, uint32_t& r2, uint32_t& r3,
                                        uint32_t addr) {
    asm volatile("ldmatrix.sync.aligned.m8n8.x4.shared.b16 {%0,%1,%2,%3}, [%4];"
                 : "=r"(r0), "=r"(r1), "=r"(r2), "=r"(r3) : "r"(addr));
}
__device__ __forceinline__ void mma16816(float* d, uint32_t a0, uint32_t a1, uint32_t a2,
                                         uint32_t a3, uint32_t b0, uint32_t b1) {
    asm volatile(
        "mma.sync.aligned.m16n8k16.row.col.f32.f16.f16.f32 "
        "{%0,%1,%2,%3}, {%4,%5,%6,%7}, {%8,%9}, {%0,%1,%2,%3};"
        : "+f"(d[0]), "+f"(d[1]), "+f"(d[2]), "+f"(d[3])
        : "r"(a0), "r"(a1), "r"(a2), "r"(a3), "r"(b0), "r"(b1));
}

// ---------------- k_route: zero pads/flags + router ----------------
__global__ void k_route(const float* __restrict__ gating) {
    int b = blockIdx.x, tid = threadIdx.x;
    if (b < ZB) {
        int i = b * 256 + tid;
        g_pair_tok[i] = 0;
        g_pair_coef[i] = 0.f;
        if (i == 0) g_flag = 0;
    } else {
        // router: top-2 softmax, renormalized (denominator cancels)
        int t = (b - ZB) * 256 + tid;
        float l[NE];
#pragma unroll
        for (int e = 0; e < NE; e++) l[e] = gating[t * NE + e];
        int i0 = 0; float b0 = l[0];
#pragma unroll
        for (int e = 1; e < NE; e++) if (l[e] > b0) { b0 = l[e]; i0 = e; }
        int i1 = -1; float b1 = -3.4e38f;
#pragma unroll
        for (int e = 0; e < NE; e++) if (e != i0 && l[e] > b1) { b1 = l[e]; i1 = e; }
        float r = __expf(b1 - b0);
        float inv = 1.f / (1.f + r);
        g_tk_idx[t * 2] = i0;  g_tk_idx[t * 2 + 1] = i1;
        g_tk_w[t * 2] = inv;   g_tk_w[t * 2 + 1] = r * inv;
    }
}

// ---------------- k_mega: scatter | xconv | wconv (mutually independent) -----
__global__ void __launch_bounds__(256, 8)
k_mega(const float* __restrict__ x, const float* __restrict__ w1,
       const float* __restrict__ w2) {
    int b = blockIdx.x, tid = threadIdx.x;
    if (b < RB) {
        // ---- scatter role (block0 computes hist+offsets, others spin) ----
        if (b == 0) {
            __shared__ int hist[NE];
            if (tid < NE) hist[tid] = 0;
            __syncthreads();
            for (int i = tid; i < TOK * 2; i += 256) atomicAdd(&hist[g_tk_idx[i]], 1);
            __syncthreads();
            if (tid == 0) {
                int off = 0, ntl = 0;
                for (int e = 0; e < NE; e++) {
                    int c = hist[e];
                    g_cur[e] = off;
                    int mts = (c + 127) >> 7;
                    for (int j = 0; j < mts; j++) {
                        g_tile_e[ntl] = e; g_tile_m0[ntl] = off + j * 128; ntl++;
                    }
                    off += mts * 128;
                }
                g_nmt = ntl;
                __threadfence();
                atomicExch(&g_flag, 1);
            }
        }
        if (tid == 0) { while (atomicAdd(&g_flag, 0) == 0) { __nanosleep(100); } }
        __syncthreads();
        int t = b * 256 + tid;
#pragma unroll
        for (int k = 0; k < 2; k++) {
            int e = g_tk_idx[t * 2 + k];
            int pos = atomicAdd(&g_cur[e], 1);
            g_pair_tok[pos] = t;
            g_pair_coef[pos] = g_tk_w[t * 2 + k];
            g_tok_pos[t * 2 + k] = pos;
        }
    } else if (b < RB + XB) {
        // ---- xconv role: x fp32 -> fp16 (ungathered) ----
        int i = (b - RB) * 256 + tid;
        float4 v = ((const float4*)x)[i];
        __half2 hh0 = __halves2half2(__float2half_rn(v.x), __float2half_rn(v.y));
        __half2 hh1 = __halves2half2(__float2half_rn(v.z), __float2half_rn(v.w));
        uint2 uh; uh.x = *(uint32_t*)&hh0; uh.y = *(uint32_t*)&hh1;
        *(uint2*)(g_xh + (size_t)i * 4) = uh;
    } else {
        // ---- wconv role: fp32 -> fp16 weights ----
        int i = (b - RB - XB) * 256 + tid;
        const float4* src; __half* dst; int q;
        if (i < W1Q) { src = (const float4*)w1; dst = g_w1h; q = i; }
        else         { src = (const float4*)w2; dst = g_w2h; q = i - W1Q; }
        float4 v = src[q];
        __half2 h01 = __halves2half2(__float2half_rn(v.x), __float2half_rn(v.y));
        __half2 h23 = __halves2half2(__float2half_rn(v.z), __float2half_rn(v.w));
        uint2 u; u.x = *(uint32_t*)&h01; u.y = *(uint32_t*)&h23;
        *(uint2*)(dst + (size_t)q * 4) = u;
    }
}

__global__ void k_combine(float* __restrict__ out) {
    int idx = blockIdx.x * blockDim.x + threadIdx.x;   // float4 outputs, TOK*256 total
    if (idx >= TOK * 256) return;
    int t = idx >> 8;
    int c4 = idx & 255;
    int p0 = g_tok_pos[t * 2];
    int p1 = g_tok_pos[t * 2 + 1];
    uint2 ua = *(const uint2*)(g_yh + (size_t)p0 * 1024 + c4 * 4);
    uint2 ub = *(const uint2*)(g_yh + (size_t)p1 * 1024 + c4 * 4);
    float2 a0 = __half22float2(*(__half2*)&ua.x);
    float2 a1 = __half22float2(*(__half2*)&ua.y);
    float2 b0 = __half22float2(*(__half2*)&ub.x);
    float2 b1 = __half22float2(*(__half2*)&ub.y);
    float4 o;
    o.x = a0.x + b0.x; o.y = a0.y + b0.y;
    o.z = a1.x + b1.x; o.w = a1.y + b1.y;
    ((float4*)out)[idx] = o;
}

// ---------------- GEMM (R12 configuration — compiler-scheduled inner loop) ---
// CTA: 128 threads = 4 warps (2M x 2N), CTA tile 128(M) x 64(N-rows), K=64.
// Warp tile 64x32 (acc[4][4][4], 158 regs). Stage = 24KB, NSTG=3, 3 CTAs/SM
// = 3 independent warps/SMSP (measured optimum: tensor ~77%).
// STAGE 1: A rows gathered from ungathered g_xh; tokens fetched by direct LDG
//   (broadcast within 8-thread groups). B rows interleave gate/up in 16-row
//   blocks: loader rows r=r0+16j => blk=j, w=r0; offB = base + BC1[j].
//   Warp-local SwiGLU pairing acc[i] <-> acc[i+2] on identical output cols.
// STAGE 2: A = g_hh rows m0+r; B rows nt*64 + r => offB = base + j*16K.
// Grid: nt fastest => concurrent CTAs share A tiles in L2.
#define SM_STG 1024
#define SB_OF  16384
#define STGSZ  24576
#define NSTG   3
#define SMEMB  (SM_STG + NSTG * STGSZ)   // 74752

template <int STAGE>
__global__ void __launch_bounds__(128, 3)
k_gemm(const float* __restrict__ w1s, const float* __restrict__ w2s) {
    const int NT = (STAGE == 1) ? 32 : 16;
    int bmt = blockIdx.x / NT;
    int nt  = blockIdx.x % NT;
    if (bmt >= g_nmt) return;
    int e  = g_tile_e[bmt];
    int m0 = g_tile_m0[bmt];

    extern __shared__ __align__(1024) char smem[];
    uint32_t sb = smem_u32(smem);
    int tid = threadIdx.x, lane = tid & 31, wid = tid >> 5;
    int wm = wid >> 1, wn = wid & 1;

    const __half* A = (STAGE == 1) ? g_xh : g_hh;
    const __half* W = (STAGE == 1) ? g_w1h : g_w2h;

    int r0 = tid >> 3, c0 = tid & 7;
    uint32_t dA0 = swz((uint32_t)(r0 * 128 + c0 * 16));   // byte offset, +2048/j
    uint32_t offA[8];                                     // half-element offsets
#pragma unroll
    for (int j = 0; j < 8; j++) {
        int row = (STAGE == 1) ? g_pair_tok[m0 + r0 + 16 * j] : (m0 + r0 + 16 * j);
        offA[j] = (uint32_t)row * 1024 + c0 * 8;
    }
    // B base: rows r=r0+16j (j<4). STAGE1: blk=j, w=r0.
    uint32_t offB0 = (STAGE == 1)
        ? (uint32_t)(e * 2048 + nt * 32 + r0) * 1024 + c0 * 8
        : (uint32_t)(e * 1024 + nt * 64 + r0) * 1024 + c0 * 8;
    const uint32_t BC1_0 = 0u, BC1_1 = 1024u * 1024u, BC1_2 = 16u * 1024u,
                   BC1_3 = 1040u * 1024u;

    float acc[4][4][4];
#pragma unroll
    for (int a = 0; a < 4; a++)
#pragma unroll
        for (int b = 0; b < 4; b++)
#pragma unroll
            for (int c = 0; c < 4; c++) acc[a][b][c] = 0.f;

#define LOAD_CHUNK(base, ko)                                                     \
    do {                                                                         \
        _Pragma("unroll")                                                        \
        for (int j = 0; j < 8; j++)                                              \
            cp16((base) + dA0 + j * 2048, A + offA[j] + (ko));                   \
        if (STAGE == 1) {                                                        \
            cp16((base) + SB_OF + dA0 + 0 * 2048, W + offB0 + BC1_0 + (ko));     \
            cp16((base) + SB_OF + dA0 + 1 * 2048, W + offB0 + BC1_1 + (ko));     \
            cp16((base) + SB_OF + dA0 + 2 * 2048, W + offB0 + BC1_2 + (ko));     \
            cp16((base) + SB_OF + dA0 + 3 * 2048, W + offB0 + BC1_3 + (ko));     \
        } else {                                                                 \
            _Pragma("unroll")                                                    \
            for (int j = 0; j < 4; j++)                                          \
                cp16((base) + SB_OF + dA0 + j * 2048, W + offB0 + j * 16384 + (ko)); \
        }                                                                        \
        CP_COMMIT();                                                             \
    } while (0)

    // prologue: load chunks 0,1
    LOAD_CHUNK(sb + SM_STG, 0);
    LOAD_CHUNK(sb + SM_STG + STGSZ, 64);

    int buf = 0;      // buffer index of current chunk kc (kc % 3)
#pragma unroll 1
    for (int kc = 0; kc < 16; kc++) {
        if (kc + 2 < 16) {
            int nb = buf + 2; if (nb >= NSTG) nb -= NSTG;
            LOAD_CHUNK(sb + SM_STG + nb * STGSZ, (kc + 2) * 64);
            CP_WAIT(2);
        } else if (kc + 1 < 16) {
            CP_WAIT(1);
        } else {
            CP_WAIT(0);
        }
        __syncthreads();

        uint32_t bufb = sb + SM_STG + buf * STGSZ;
        int grp = lane >> 3, lr = lane & 7;
#pragma unroll
        for (int ks = 0; ks < 4; ks++) {
            // B fragments: 2 x ldmatrix.x4 (non-trans) covering 4 n8-tiles
            uint32_t bf[4][2];
#pragma unroll
            for (int p = 0; p < 2; p++) {
                int nrow = wn * 32 + p * 16 + ((grp >> 1) << 3) + lr;
                int ko = ks * 16 + ((grp & 1) << 3);
                uint32_t ad = bufb + SB_OF + swz((uint32_t)(nrow * 128 + ko * 2));
                ldsm_x4(bf[2 * p][0], bf[2 * p][1], bf[2 * p + 1][0], bf[2 * p + 1][1], ad);
            }
#pragma unroll
            for (int mt = 0; mt < 4; mt++) {
                int mrow = wm * 64 + mt * 16 + ((grp & 1) << 3) + lr;
                int ko = ks * 16 + ((grp >> 1) << 3);
                uint32_t ad = bufb + swz((uint32_t)(mrow * 128 + ko * 2));
                uint32_t a0, a1, a2, a3;
                ldsm_x4(a0, a1, a2, a3, ad);
#pragma unroll
                for (int n8 = 0; n8 < 4; n8++)
                    mma16816(acc[mt][n8], a0, a1, a2, a3, bf[n8][0], bf[n8][1]);
            }
        }
        __syncthreads();
        buf++; if (buf >= NSTG) buf = 0;
    }

    // ---------------- epilogue ----------------
    if (STAGE == 1) {
        float s1 = w1s[e];
#pragma unroll
        for (int mt = 0; mt < 4; mt++) {
            int r0e = m0 + wm * 64 + mt * 16 + (lane >> 2);
#pragma unroll
            for (int i = 0; i < 2; i++) {
                int col = nt * 32 + wn * 16 + i * 8 + (lane & 3) * 2;
#pragma unroll
                for (int hh = 0; hh < 2; hh++) {
                    int rr = r0e + hh * 8;
                    float g0 = s1 * acc[mt][i][2 * hh + 0];
                    float g1 = s1 * acc[mt][i][2 * hh + 1];
                    float u0 = s1 * acc[mt][i + 2][2 * hh + 0];
                    float u1 = s1 * acc[mt][i + 2][2 * hh + 1];
                    float h0 = g0 * (1.f / (1.f + __expf(-g0))) * u0;
                    float h1 = g1 * (1.f / (1.f + __expf(-g1))) * u1;
                    *(__half2*)(g_hh + (size_t)rr * 1024 + col) =
                        __halves2half2(__float2half_rn(h0), __float2half_rn(h1));
                }
            }
        }
    } else {
        float s2 = w2s[e];
#pragma unroll
        for (int mt = 0; mt < 4; mt++) {
            int r0e = m0 + wm * 64 + mt * 16 + (lane >> 2);
#pragma unroll
            for (int hh = 0; hh < 2; hh++) {
                int rr = r0e + hh * 8;
                float sc = g_pair_coef[rr] * s2;
#pragma unroll
                for (int i = 0; i < 4; i++) {
                    int col = nt * 64 + wn * 32 + i * 8 + (lane & 3) * 2;
                    float y0 = sc * acc[mt][i][2 * hh + 0];
                    float y1 = sc * acc[mt][i][2 * hh + 1];
                    *(__half2*)(g_yh + (size_t)rr * 1024 + col) =
                        __halves2half2(__float2half_rn(y0), __float2half_rn(y1));
                }
            }
        }
    }
#undef LOAD_CHUNK
}

// ---------------- launch ----------------
extern "C" void kernel_launch(void* const* d_in, const int* in_sizes, int n_in,
                              void* d_out, int out_size) {
    const float* x      = (const float*)d_in[0];
    const float* gating = (const float*)d_in[1];
    const float* w1     = (const float*)d_in[2];
    const float* w2     = (const float*)d_in[3];
    const float* w1s    = (const float*)d_in[4];
    const float* w2s    = (const float*)d_in[5];
    float* out = (float*)d_out;

    cudaFuncSetAttribute(k_gemm<1>, cudaFuncAttributeMaxDynamicSharedMemorySize, SMEMB);
    cudaFuncSetAttribute(k_gemm<2>, cudaFuncAttributeMaxDynamicSharedMemorySize, SMEMB);

    k_route<<<ZB + RB, 256>>>(gating);
    k_mega<<<RB + XB + WCB, 256>>>(x, w1, w2);
    k_gemm<1><<<MAXMT * 32, 128, SMEMB>>>(w1s, w2s);   // ncu captures this launch
    k_gemm<2><<<MAXMT * 16, 128, SMEMB>>>(w1s, w2s);
    k_combine<<<TOK, 256>>>(out);
}